// round 10
// baseline (speedup 1.0000x reference)
#include <cuda_runtime.h>
#include <cstdint>

// GaussianPooling: out[n,c] = sum_{dy,dx} fm[c, y+dy, x+dx] * kern[dy,dx]
// fm: [512,256,256] f32, keypoints: [4096,2] int (x,y), out: [4096,512] f32.
// Separable 5x5 Gaussian (sigma=2).
//
// prep: 256 blocks (16 stripes x 16 keypoint-slices) bin keypoints into
//       per-(stripe,part) queues; early PDL trigger.
// main: block = (stripe of 16 rows, channel pair), 5 blocks/SM.
//       Phase 1: 40x cp.async.bulk (TMA engine) 1KB row copies -> SMEM raw
//                tile, one mbarrier. No per-thread LDG streaming at all.
//       Phase 2: warp-per-part keypoint gather straight from the raw tile
//                (5x5 separable dot), STG.64 output.

#define C_DIM 512
#define H_DIM 256
#define W_DIM 256
#define N_KP  4096
#define PLANE (H_DIM * W_DIM)
#define STRIPE_ROWS 16
#define N_STRIPES (H_DIM / STRIPE_ROWS)          // 16
#define N_PARTS 16
#define PART_KP (N_KP / N_PARTS)                 // 256
#define RAW_ROWS 20                              // 16 + 2 halo each side
#define RAWS 264                                 // row stride (floats), 1056B
#define CH_OFF (RAW_ROWS * RAWS)                 // 5280 floats per channel
#define CG 2
#define SMEM_BYTES (CG * CH_OFF * 4)             // 42240
#define TX_BYTES (CG * RAW_ROWS * W_DIM * 4)     // 40960

__device__ int g_q[N_STRIPES * N_PARTS * PART_KP];  // packed (n<<16)|(x<<8)|y
__device__ int g_qcnt[N_STRIPES * N_PARTS];

static __device__ __forceinline__ float gval(float i) {
    float d = i - 2.0f;
    return __expf(-d * d * 0.125f);              // exp(-d^2/(2*sigma^2))
}

static __device__ __forceinline__ uint32_t smem_u32(const void* p) {
    return (uint32_t)__cvta_generic_to_shared(p);
}

// grid = 16 stripes x 16 parts. Each block scans its 256-keypoint slice for
// its stripe. dtype detect per slice: words kp32[2n+1] are y (int32 case,
// random nonzero somewhere in slice) or int64 high halves (all zero).
__global__ void prep_kp_kernel(const int* __restrict__ kp32)
{
    __shared__ int s_or[256];
    __shared__ int s_flag;
    __shared__ int s_cnt;
    const int t      = threadIdx.x;
    const int stripe = blockIdx.x >> 4;
    const int part   = blockIdx.x & (N_PARTS - 1);
    const int n      = part * PART_KP + t;

    s_or[t] = kp32[2 * n + 1];
    if (t == 0) s_cnt = 0;
    __syncthreads();
    for (int s = 128; s > 0; s >>= 1) {
        if (t < s) s_or[t] |= s_or[t + s];
        __syncthreads();
    }
    if (t == 0) s_flag = s_or[0];
    __syncthreads();
    const bool is_i32 = (s_flag != 0);

    int x, y;
    if (is_i32) { x = kp32[2 * n];     y = kp32[2 * n + 1]; }
    else        { x = kp32[4 * n];     y = kp32[4 * n + 2]; }
    x = min(max(x, 2), W_DIM - 3);
    y = min(max(y, 2), H_DIM - 3);

    if ((y >> 4) == stripe) {
        int idx = atomicAdd(&s_cnt, 1);
        g_q[(stripe * N_PARTS + part) * PART_KP + idx] =
            (n << 16) | (x << 8) | y;
    }
    __syncthreads();
    if (t == 0) g_qcnt[stripe * N_PARTS + part] = s_cnt;

    cudaTriggerProgrammaticLaunchCompletion();
}

__global__ void __launch_bounds__(256)
gauss_pool_kernel(const float* __restrict__ fm, float* __restrict__ out)
{
    extern __shared__ float s_raw[];             // [CG][RAW_ROWS][RAWS]
    __shared__ __align__(16) float s_gx[4][8];
    __shared__ __align__(8)  unsigned long long s_mbar;

    const int cg0    = (blockIdx.x & 255) * CG;
    const int stripe = blockIdx.x >> 8;
    const int t      = threadIdx.x;
    const int row0   = stripe * STRIPE_ROWS - 2;

    const uint32_t mbar = smem_u32(&s_mbar);

    if (t == 0) {
        asm volatile("mbarrier.init.shared.b64 [%0], %1;"
                     :: "r"(mbar), "r"(1u) : "memory");
    }
    __syncthreads();

    if (t == 0) {
        asm volatile("mbarrier.arrive.expect_tx.shared.b64 _, [%0], %1;"
                     :: "r"(mbar), "r"((uint32_t)TX_BYTES) : "memory");
    }
    // 40 bulk copies: 2 channels x 20 rows, 1KB each (TMA engine).
    if (t < CG * RAW_ROWS) {
        const int ch  = t >= RAW_ROWS;
        const int row = ch ? t - RAW_ROWS : t;
        const int gr  = min(max(row0 + row, 0), H_DIM - 1);  // legal addr;
        // clamped rows are never read (keypoint y is clipped to [2,253])
        const float* src = fm + (size_t)(cg0 + ch) * PLANE + gr * W_DIM;
        const uint32_t dst =
            smem_u32(s_raw) + (uint32_t)(ch * CH_OFF + row * RAWS) * 4u;
        asm volatile(
            "cp.async.bulk.shared::cta.global.mbarrier::complete_tx::bytes "
            "[%0], [%1], %2, [%3];"
            :: "r"(dst), "l"(src), "r"((uint32_t)(W_DIM * 4)), "r"(mbar)
            : "memory");
    }

    const float inv_norm =
        1.0f / (gval(0.f) + gval(1.f) + gval(2.f) + gval(3.f) + gval(4.f));

    if (t < 32) {
        int off = t >> 3, j = t & 7;
        int i = j - off;
        s_gx[off][j] = (i >= 0 && i < 5) ? gval((float)i) * inv_norm : 0.0f;
    }

    float gy[5];
    #pragma unroll
    for (int r = 0; r < 5; ++r) gy[r] = gval((float)r) * inv_norm;

    cudaGridDependencySynchronize();             // queues ready (PDL)
    __syncthreads();                             // s_gx visible

    // wait for the raw tile (parity 0; acquire orders subsequent LDS)
    {
        uint32_t done;
        asm volatile(
            "{\n\t.reg .pred p;\n\t"
            "mbarrier.try_wait.parity.acquire.cta.shared::cta.b64 p, [%1], %2;\n\t"
            "selp.b32 %0, 1, 0, p;\n\t}"
            : "=r"(done) : "r"(mbar), "r"(0u) : "memory");
        if (!done) {
            asm volatile(
                "{\n\t.reg .pred P1;\n\t"
                "W_%=:\n\t"
                "mbarrier.try_wait.parity.acquire.cta.shared::cta.b64 P1, [%0], %1, 0x989680;\n\t"
                "@P1 bra.uni D_%=;\n\t"
                "bra.uni W_%=;\n\t"
                "D_%=:\n\t}"
                :: "r"(mbar), "r"(0u) : "memory");
        }
    }

    // ---- Phase 2: one warp per part (16 parts, 8 warps x 2 rounds) ----
    const int warp = t >> 5;
    const int lane = t & 31;

    #pragma unroll 1
    for (int pp = 0; pp < N_PARTS / 8; ++pp) {
        const int p   = warp + pp * 8;
        const int qi  = stripe * N_PARTS + p;
        const int cnt = g_qcnt[qi];
        const int* q  = &g_q[qi * PART_KP];

        for (int i = lane; i < cnt; i += 32) {
            const int v = q[i];
            const int y = v & 255;
            const int x = (v >> 8) & 255;
            const int n = v >> 16;

            const int w0c = x - 2;
            const int a   = w0c & ~3;
            const int off = w0c - a;
            const int yl  = y - stripe * STRIPE_ROWS;   // 0..15

            float4 G0 = *(const float4*)&s_gx[off][0];
            float4 G1 = *(const float4*)&s_gx[off][4];

            // raw local row for tap r (0..4) is yl + r
            const float* b0 = s_raw + yl * RAWS + a;
            const float* b1 = b0 + CH_OFF;

            float acc0 = 0.0f, acc1 = 0.0f;
            #pragma unroll
            for (int r = 0; r < 5; ++r) {
                float4 A = *(const float4*)(b0 + r * RAWS);
                float4 B = *(const float4*)(b0 + r * RAWS + 4);
                float rs0 = G0.x * A.x + G0.y * A.y + G0.z * A.z + G0.w * A.w
                          + G1.x * B.x + G1.y * B.y + G1.z * B.z + G1.w * B.w;
                acc0 = fmaf(gy[r], rs0, acc0);
                float4 C = *(const float4*)(b1 + r * RAWS);
                float4 D = *(const float4*)(b1 + r * RAWS + 4);
                float rs1 = G0.x * C.x + G0.y * C.y + G0.z * C.z + G0.w * C.w
                          + G1.x * D.x + G1.y * D.y + G1.z * D.z + G1.w * D.w;
                acc1 = fmaf(gy[r], rs1, acc1);
            }

            float2 res = make_float2(acc0, acc1);
            *(float2*)&out[n * C_DIM + cg0] = res;
        }
    }
}

extern "C" void kernel_launch(void* const* d_in, const int* in_sizes, int n_in,
                              void* d_out, int out_size)
{
    const float* fm   = (const float*)d_in[0];
    const int*   kp32 = (const int*)d_in[1];
    float*       out  = (float*)d_out;

    cudaFuncSetAttribute(gauss_pool_kernel,
                         cudaFuncAttributeMaxDynamicSharedMemorySize,
                         SMEM_BYTES);

    prep_kp_kernel<<<N_STRIPES * N_PARTS, 256>>>(kp32);

    cudaLaunchConfig_t cfg = {};
    cfg.gridDim  = dim3(N_STRIPES * (C_DIM / CG));
    cfg.blockDim = dim3(256);
    cfg.dynamicSmemBytes = SMEM_BYTES;
    cfg.stream = 0;
    cudaLaunchAttribute attr[1];
    attr[0].id = cudaLaunchAttributeProgrammaticStreamSerialization;
    attr[0].val.programmaticStreamSerializationAllowed = 1;
    cfg.attrs = attr;
    cfg.numAttrs = 1;
    cudaLaunchKernelEx(&cfg, gauss_pool_kernel, fm, out);
}

// round 11
// speedup vs baseline: 1.4645x; 1.4645x over previous
#include <cuda_runtime.h>
#include <cstdint>

// GaussianPooling: out[n,c] = sum_{dy,dx} fm[c, y+dy, x+dx] * kern[dy,dx]
// fm: [512,256,256] f32, keypoints: [4096,2] int (x,y), out: [4096,512] f32.
// Separable 5x5 Gaussian (sigma=2).
//
// prep: 128 blocks (8 stripes x 16 keypoint-slices) bin keypoints into
//       per-(stripe,part) queues; early PDL trigger.
// main: block = (stripe of 32 rows, channel pair), 3 blocks/SM.
//       Phase 1: 72x cp.async.bulk 1KB row copies -> SMEM raw tile (TMA
//                engine, one mbarrier; no LDG streaming / no long-scoreboard).
//       Phase 1b: vertical 5-tap conv SMEM->SMEM in place (reg staging).
//       Phase 2: warp-per-part keypoint gather: 2 LDS.128 per kp per
//                channel from the V tile; STG.64 output.

#define C_DIM 512
#define H_DIM 256
#define W_DIM 256
#define N_KP  4096
#define PLANE (H_DIM * W_DIM)
#define STRIPE_ROWS 32
#define N_STRIPES (H_DIM / STRIPE_ROWS)          // 8
#define N_PARTS 16
#define PART_KP (N_KP / N_PARTS)                 // 256
#define RAW_ROWS 36                              // 32 + 2 halo each side
#define STR 260                                  // row stride floats (1040B)
#define CH_OFF (RAW_ROWS * STR)                  // 9360 floats per channel
#define CG 2
#define SMEM_BYTES (CG * CH_OFF * 4)             // 74880
#define TX_BYTES (CG * RAW_ROWS * W_DIM * 4)     // 73728

__device__ int g_q[N_STRIPES * N_PARTS * PART_KP];  // packed (n<<16)|(x<<8)|y
__device__ int g_qcnt[N_STRIPES * N_PARTS];

static __device__ __forceinline__ float gval(float i) {
    float d = i - 2.0f;
    return __expf(-d * d * 0.125f);              // exp(-d^2/(2*sigma^2))
}

static __device__ __forceinline__ uint32_t smem_u32(const void* p) {
    return (uint32_t)__cvta_generic_to_shared(p);
}

// grid = 8 stripes x 16 parts. Each block scans its 256-keypoint slice for
// its stripe. dtype detect per slice: words kp32[2n+1] are y (int32 case,
// random nonzero somewhere in slice) or int64 high halves (all zero).
__global__ void prep_kp_kernel(const int* __restrict__ kp32)
{
    __shared__ int s_or[256];
    __shared__ int s_flag;
    __shared__ int s_cnt;
    const int t      = threadIdx.x;
    const int stripe = blockIdx.x >> 4;
    const int part   = blockIdx.x & (N_PARTS - 1);
    const int n      = part * PART_KP + t;

    s_or[t] = kp32[2 * n + 1];
    if (t == 0) s_cnt = 0;
    __syncthreads();
    for (int s = 128; s > 0; s >>= 1) {
        if (t < s) s_or[t] |= s_or[t + s];
        __syncthreads();
    }
    if (t == 0) s_flag = s_or[0];
    __syncthreads();
    const bool is_i32 = (s_flag != 0);

    int x, y;
    if (is_i32) { x = kp32[2 * n];     y = kp32[2 * n + 1]; }
    else        { x = kp32[4 * n];     y = kp32[4 * n + 2]; }
    x = min(max(x, 2), W_DIM - 3);
    y = min(max(y, 2), H_DIM - 3);

    if ((y >> 5) == stripe) {
        int idx = atomicAdd(&s_cnt, 1);
        g_q[(stripe * N_PARTS + part) * PART_KP + idx] =
            (n << 16) | (x << 8) | y;
    }
    __syncthreads();
    if (t == 0) g_qcnt[stripe * N_PARTS + part] = s_cnt;

    cudaTriggerProgrammaticLaunchCompletion();
}

__global__ void __launch_bounds__(256, 3)
gauss_pool_kernel(const float* __restrict__ fm, float* __restrict__ out)
{
    extern __shared__ float s_v[];               // raw then in-place V tiles
    __shared__ __align__(16) float s_gx[4][8];
    __shared__ __align__(8)  unsigned long long s_mbar;

    const int cg0    = (blockIdx.x & 255) * CG;
    const int stripe = blockIdx.x >> 8;
    const int t      = threadIdx.x;
    const int row0   = stripe * STRIPE_ROWS - 2;

    const uint32_t mbar = smem_u32(&s_mbar);

    if (t == 0) {
        asm volatile("mbarrier.init.shared.b64 [%0], %1;"
                     :: "r"(mbar), "r"(1u) : "memory");
    }
    __syncthreads();

    if (t == 0) {
        asm volatile("mbarrier.arrive.expect_tx.shared.b64 _, [%0], %1;"
                     :: "r"(mbar), "r"((uint32_t)TX_BYTES) : "memory");
    }
    // 72 bulk copies: 2 channels x 36 rows, 1KB each (TMA engine).
    if (t < CG * RAW_ROWS) {
        const int ch  = t / RAW_ROWS;
        const int row = t - ch * RAW_ROWS;
        const int gr  = min(max(row0 + row, 0), H_DIM - 1);  // legal addr;
        // clamped rows are never read (keypoint y is clipped to [2,253])
        const float* src = fm + (size_t)(cg0 + ch) * PLANE + gr * W_DIM;
        const uint32_t dst =
            smem_u32(s_v) + (uint32_t)(ch * CH_OFF + row * STR) * 4u;
        asm volatile(
            "cp.async.bulk.shared::cta.global.mbarrier::complete_tx::bytes "
            "[%0], [%1], %2, [%3];"
            :: "r"(dst), "l"(src), "r"((uint32_t)(W_DIM * 4)), "r"(mbar)
            : "memory");
    }

    const float inv_norm =
        1.0f / (gval(0.f) + gval(1.f) + gval(2.f) + gval(3.f) + gval(4.f));

    if (t < 32) {
        int off = t >> 3, j = t & 7;
        int i = j - off;
        s_gx[off][j] = (i >= 0 && i < 5) ? gval((float)i) * inv_norm : 0.0f;
    }

    const float g0 = gval(0.f) * inv_norm;
    const float g1 = gval(1.f) * inv_norm;
    const float g2 = gval(2.f) * inv_norm;

    // wait for the raw tile (parity 0; acquire orders subsequent LDS)
    {
        uint32_t done;
        asm volatile(
            "{\n\t.reg .pred p;\n\t"
            "mbarrier.try_wait.parity.acquire.cta.shared::cta.b64 p, [%1], %2;\n\t"
            "selp.b32 %0, 1, 0, p;\n\t}"
            : "=r"(done) : "r"(mbar), "r"(0u) : "memory");
        if (!done) {
            asm volatile(
                "{\n\t.reg .pred P1;\n\t"
                "W_%=:\n\t"
                "mbarrier.try_wait.parity.acquire.cta.shared::cta.b64 P1, [%0], %1, 0x989680;\n\t"
                "@P1 bra.uni D_%=;\n\t"
                "bra.uni W_%=;\n\t"
                "D_%=:\n\t}"
                :: "r"(mbar), "r"(0u) : "memory");
        }
    }

    // ---- Phase 1b: vertical conv SMEM->SMEM, in place ----
    // V row vi (overwrites raw row vi) = conv of raw rows vi..vi+4, i.e.
    // centered at global row stripe*32 + vi. Two 16-row halves per channel;
    // stage 8 raw rows to registers, sync, then write 4 V rows per thread.
    {
        const int strip = t & 63;                // float4 column
        const int chunk = t >> 6;                // 0..3

        #pragma unroll
        for (int cg = 0; cg < CG; ++cg) {
            float* tile = s_v + cg * CH_OFF;
            #pragma unroll
            for (int half = 0; half < 2; ++half) {
                const int vb = half * 16 + chunk * 4;   // first V row
                float4 w[8];
                #pragma unroll
                for (int k = 0; k < 8; ++k)
                    w[k] = *(const float4*)&tile[(vb + k) * STR + strip * 4];
                __syncthreads();                 // all stages before writes
                #pragma unroll
                for (int j = 0; j < 4; ++j) {
                    float4 r;
                    r.x = g0 * (w[j].x + w[j+4].x) + g1 * (w[j+1].x + w[j+3].x) + g2 * w[j+2].x;
                    r.y = g0 * (w[j].y + w[j+4].y) + g1 * (w[j+1].y + w[j+3].y) + g2 * w[j+2].y;
                    r.z = g0 * (w[j].z + w[j+4].z) + g1 * (w[j+1].z + w[j+3].z) + g2 * w[j+2].z;
                    r.w = g0 * (w[j].w + w[j+4].w) + g1 * (w[j+1].w + w[j+3].w) + g2 * w[j+2].w;
                    *(float4*)&tile[(vb + j) * STR + strip * 4] = r;
                }
                __syncthreads();                 // writes before next stage
            }
        }
    }

    cudaGridDependencySynchronize();             // queues ready (PDL)

    // ---- Phase 2: one warp per part (16 parts, 8 warps x 2 rounds) ----
    const int warp = t >> 5;
    const int lane = t & 31;

    #pragma unroll 1
    for (int pp = 0; pp < N_PARTS / 8; ++pp) {
        const int p   = warp + pp * 8;
        const int qi  = stripe * N_PARTS + p;
        const int cnt = g_qcnt[qi];
        const int* q  = &g_q[qi * PART_KP];

        for (int i = lane; i < cnt; i += 32) {
            const int v = q[i];
            const int y = v & 255;
            const int x = (v >> 8) & 255;
            const int n = v >> 16;

            const int w0c = x - 2;
            const int a   = w0c & ~3;
            const int off = w0c - a;
            const int yl  = y - stripe * STRIPE_ROWS;   // 0..31

            float4 G0 = *(const float4*)&s_gx[off][0];
            float4 G1 = *(const float4*)&s_gx[off][4];

            const float* b0 = s_v + yl * STR + a;
            const float* b1 = b0 + CH_OFF;

            float4 A = *(const float4*)(b0);
            float4 B = *(const float4*)(b0 + 4);
            float4 C = *(const float4*)(b1);
            float4 D = *(const float4*)(b1 + 4);

            float2 res;
            res.x = G0.x * A.x + G0.y * A.y + G0.z * A.z + G0.w * A.w
                  + G1.x * B.x + G1.y * B.y + G1.z * B.z + G1.w * B.w;
            res.y = G0.x * C.x + G0.y * C.y + G0.z * C.z + G0.w * C.w
                  + G1.x * D.x + G1.y * D.y + G1.z * D.z + G1.w * D.w;

            *(float2*)&out[n * C_DIM + cg0] = res;
        }
    }
}

extern "C" void kernel_launch(void* const* d_in, const int* in_sizes, int n_in,
                              void* d_out, int out_size)
{
    const float* fm   = (const float*)d_in[0];
    const int*   kp32 = (const int*)d_in[1];
    float*       out  = (float*)d_out;

    cudaFuncSetAttribute(gauss_pool_kernel,
                         cudaFuncAttributeMaxDynamicSharedMemorySize,
                         SMEM_BYTES);

    prep_kp_kernel<<<N_STRIPES * N_PARTS, 256>>>(kp32);

    cudaLaunchConfig_t cfg = {};
    cfg.gridDim  = dim3(N_STRIPES * (C_DIM / CG));
    cfg.blockDim = dim3(256);
    cfg.dynamicSmemBytes = SMEM_BYTES;
    cfg.stream = 0;
    cudaLaunchAttribute attr[1];
    attr[0].id = cudaLaunchAttributeProgrammaticStreamSerialization;
    attr[0].val.programmaticStreamSerializationAllowed = 1;
    cfg.attrs = attr;
    cfg.numAttrs = 1;
    cudaLaunchKernelEx(&cfg, gauss_pool_kernel, fm, out);
}